// round 6
// baseline (speedup 1.0000x reference)
#include <cuda_runtime.h>

// Problem sizes
#define NB   148      // persistent grid (<= 152 SMs on GB300, all co-resident)
#define NT   256
#define Bb   16
#define Tt   2000
#define Cc   128
#define Gg   512
#define Hh   512
#define Vv   256

// ---------------- global scratch (no allocations allowed) ----------------
__device__ __align__(16) float g_h[2][Bb * Gg];    // double-buffered hidden state
__device__ __align__(16) float g_hid[Bb * Hh];
__device__ __align__(16) float g_val[Bb * Vv];     // logits + gumbel (for argmax)
__device__ unsigned int        g_cnt;              // barrier arrival counter
__device__ unsigned long long  g_gen;              // barrier generation (monotonic across launches)

struct __align__(16) Smem {
    float sh[Bb * Gg];     // 32KB: staged h (P1) / h_new (P2) / hid (P3)
    float sx[Bb * Cc];     // 8KB : staged x = cond_t + embedding[prev]
    int   sprev[Bb];
    unsigned long long gen0;
};

// ---------------- threefry2x32 (exact JAX semantics) ----------------
__device__ __forceinline__ unsigned rotl32(unsigned x, int r) {
    return (x << r) | (x >> (32 - r));
}

__device__ __forceinline__ void tf2x32(unsigned k0, unsigned k1,
                                       unsigned x0, unsigned x1,
                                       unsigned& o0, unsigned& o1) {
    unsigned ks2 = k0 ^ k1 ^ 0x1BD11BDAu;
    x0 += k0; x1 += k1;
    // rounds 1-4 (rot 13,15,26,6)
    x0 += x1; x1 = rotl32(x1, 13); x1 ^= x0;
    x0 += x1; x1 = rotl32(x1, 15); x1 ^= x0;
    x0 += x1; x1 = rotl32(x1, 26); x1 ^= x0;
    x0 += x1; x1 = rotl32(x1, 6);  x1 ^= x0;
    x0 += k1; x1 += ks2 + 1u;
    // rounds 5-8 (rot 17,29,16,24)
    x0 += x1; x1 = rotl32(x1, 17); x1 ^= x0;
    x0 += x1; x1 = rotl32(x1, 29); x1 ^= x0;
    x0 += x1; x1 = rotl32(x1, 16); x1 ^= x0;
    x0 += x1; x1 = rotl32(x1, 24); x1 ^= x0;
    x0 += ks2; x1 += k0 + 2u;
    // rounds 9-12
    x0 += x1; x1 = rotl32(x1, 13); x1 ^= x0;
    x0 += x1; x1 = rotl32(x1, 15); x1 ^= x0;
    x0 += x1; x1 = rotl32(x1, 26); x1 ^= x0;
    x0 += x1; x1 = rotl32(x1, 6);  x1 ^= x0;
    x0 += k0; x1 += k1 + 3u;
    // rounds 13-16
    x0 += x1; x1 = rotl32(x1, 17); x1 ^= x0;
    x0 += x1; x1 = rotl32(x1, 29); x1 ^= x0;
    x0 += x1; x1 = rotl32(x1, 16); x1 ^= x0;
    x0 += x1; x1 = rotl32(x1, 24); x1 ^= x0;
    x0 += k1; x1 += ks2 + 4u;
    // rounds 17-20
    x0 += x1; x1 = rotl32(x1, 13); x1 ^= x0;
    x0 += x1; x1 = rotl32(x1, 15); x1 ^= x0;
    x0 += x1; x1 = rotl32(x1, 26); x1 ^= x0;
    x0 += x1; x1 = rotl32(x1, 6);  x1 ^= x0;
    x0 += ks2; x1 += k0 + 5u;
    o0 = x0; o1 = x1;
}

__device__ __forceinline__ float sigmoidf_(float x) {
    return 1.0f / (1.0f + expf(-x));
}

// ---------------- grid barrier (monotonic generation, launch-safe) ----------------
__device__ __forceinline__ void grid_barrier(unsigned long long target) {
    __threadfence();      // publish this thread's prior global writes (release)
    __syncthreads();
    if (threadIdx.x == 0) {
        unsigned int c = atomicAdd(&g_cnt, 1u);
        if (c == NB - 1) {
            g_cnt = 0;
            __threadfence();
            atomicAdd(&g_gen, 1ULL);
        } else {
            while (atomicAdd(&g_gen, 0ULL) < target) { __nanosleep(40); }
        }
        __threadfence();  // acquire
    }
    __syncthreads();
}

// warp-cooperative argmax over g_val[b][0..255], first-index tie-break (jnp.argmax)
__device__ __forceinline__ int warp_argmax_b(int b, int lane) {
    float bestv = -1e30f; int besti = 0;
#pragma unroll
    for (int k = 0; k < 8; ++k) {
        int v = lane + 32 * k;
        float x = __ldcg(&g_val[b * Vv + v]);
        if (x > bestv) { bestv = x; besti = v; }
    }
#pragma unroll
    for (int off = 16; off; off >>= 1) {
        float ov = __shfl_xor_sync(0xffffffffu, bestv, off);
        int   oi = __shfl_xor_sync(0xffffffffu, besti, off);
        if (ov > bestv || (ov == bestv && oi < besti)) { bestv = ov; besti = oi; }
    }
    return besti;
}

__global__ void __launch_bounds__(NT, 1)
wavernn_persistent(const float* __restrict__ cond,
                   const float* __restrict__ h0,
                   const float* __restrict__ W_ih,
                   const float* __restrict__ W_hh,
                   const float* __restrict__ b_ih,
                   const float* __restrict__ b_hh,
                   const float* __restrict__ W_hid,
                   const float* __restrict__ b_hid,
                   const float* __restrict__ W_out,
                   const float* __restrict__ b_out,
                   const float* __restrict__ emb,
                   float* __restrict__ out) {
    __shared__ Smem sm;
    const int tid  = threadIdx.x;
    const int bid  = blockIdx.x;
    const int wid  = tid >> 5;
    const int lane = tid & 31;

    // barrier generation base for this launch (safe: gen cannot advance until
    // every block of THIS launch has arrived at barrier 1, and each block reads
    // the base before its first arrival)
    if (tid == 0) sm.gen0 = atomicAdd(&g_gen, 0ULL);
    __syncthreads();
    unsigned long long target = sm.gen0;

    float* out_logits  = out;                                // [B][T][V]
    float* out_samples = out + (size_t)Bb * Tt * Vv;         // [B][T]
    float* out_hfinal  = out + (size_t)Bb * Tt * Vv + (size_t)Bb * Tt; // [B][G]

    // ---- init: h[0] = h0 ----
    for (int i = bid * NT + tid; i < Bb * Gg; i += NB * NT)
        g_h[0][i] = h0[i];
    grid_barrier(++target);

    for (int t = 0; t < Tt; ++t) {
        const int pb = t & 1;           // g_h[pb] = current h, g_h[pb^1] = h_new

        // ================= P1 prologue: prev (argmax of last step) + stage x, h =================
        if (t == 0) {
            if (tid < Bb) sm.sprev[tid] = Vv / 2;   // mid-bucket
        } else if (wid < 8) {
#pragma unroll
            for (int rep = 0; rep < 2; ++rep) {
                int b = wid + rep * 8;
                int besti = warp_argmax_b(b, lane);
                if (lane == 0) {
                    sm.sprev[b] = besti;
                    if (bid == 0) out_samples[b * Tt + (t - 1)] = (float)besti;
                }
            }
        }
        __syncthreads();

        // stage x = cond[:, t, :] + embedding[prev]
        for (int i = tid; i < Bb * Cc; i += NT) {
            int b = i >> 7, c = i & (Cc - 1);
            sm.sx[i] = __ldg(&cond[((size_t)b * Tt + t) * Cc + c]) +
                       __ldg(&emb[(size_t)sm.sprev[b] * Cc + c]);
        }
        // stage h (cross-SM data: L2 loads)
        {
            const float4* src = (const float4*)g_h[pb];
            float4* dst = (float4*)sm.sh;
            for (int i = tid; i < (Bb * Gg) / 4; i += NT) dst[i] = __ldcg(src + i);
        }
        __syncthreads();

        // ================= P1: fused GRU gates + h update =================
        {
            const int u0 = (bid * Gg) / NB, u1 = ((bid + 1) * Gg) / NB;
            const int u  = u0 + (wid >> 1);
            if (u < u1) {
                const int b0 = (wid & 1) * 8;
                float sr[8], sz[8], si[8], shn[8];
#pragma unroll
                for (int b = 0; b < 8; ++b) { sr[b] = 0.f; sz[b] = 0.f; si[b] = 0.f; shn[b] = 0.f; }

                // x part: W_ih rows u (r), G+u (z), 2G+u (n); row = 32 float4
                {
                    float4 wr = __ldg((const float4*)(W_ih + (size_t)u * Cc) + lane);
                    float4 wz = __ldg((const float4*)(W_ih + (size_t)(Gg + u) * Cc) + lane);
                    float4 wn = __ldg((const float4*)(W_ih + (size_t)(2 * Gg + u) * Cc) + lane);
#pragma unroll
                    for (int b = 0; b < 8; ++b) {
                        float4 x4 = ((const float4*)(sm.sx + (b0 + b) * Cc))[lane];
                        sr[b] = fmaf(wr.x, x4.x, fmaf(wr.y, x4.y, fmaf(wr.z, x4.z, fmaf(wr.w, x4.w, sr[b]))));
                        sz[b] = fmaf(wz.x, x4.x, fmaf(wz.y, x4.y, fmaf(wz.z, x4.z, fmaf(wz.w, x4.w, sz[b]))));
                        si[b] = fmaf(wn.x, x4.x, fmaf(wn.y, x4.y, fmaf(wn.z, x4.z, fmaf(wn.w, x4.w, si[b]))));
                    }
                }
                // h part: W_hh rows u, G+u, 2G+u; row = 128 float4
#pragma unroll
                for (int k = 0; k < 4; ++k) {
                    int c4 = lane + 32 * k;
                    float4 wr = __ldg((const float4*)(W_hh + (size_t)u * Gg) + c4);
                    float4 wz = __ldg((const float4*)(W_hh + (size_t)(Gg + u) * Gg) + c4);
                    float4 wn = __ldg((const float4*)(W_hh + (size_t)(2 * Gg + u) * Gg) + c4);
#pragma unroll
                    for (int b = 0; b < 8; ++b) {
                        float4 h4 = ((const float4*)(sm.sh + (b0 + b) * Gg))[c4];
                        sr[b]  = fmaf(wr.x, h4.x, fmaf(wr.y, h4.y, fmaf(wr.z, h4.z, fmaf(wr.w, h4.w, sr[b]))));
                        sz[b]  = fmaf(wz.x, h4.x, fmaf(wz.y, h4.y, fmaf(wz.z, h4.z, fmaf(wz.w, h4.w, sz[b]))));
                        shn[b] = fmaf(wn.x, h4.x, fmaf(wn.y, h4.y, fmaf(wn.z, h4.z, fmaf(wn.w, h4.w, shn[b]))));
                    }
                }
                // butterfly reduce all 32 accumulators across the warp
#pragma unroll
                for (int off = 16; off; off >>= 1) {
#pragma unroll
                    for (int b = 0; b < 8; ++b) {
                        sr[b]  += __shfl_xor_sync(0xffffffffu, sr[b],  off);
                        sz[b]  += __shfl_xor_sync(0xffffffffu, sz[b],  off);
                        si[b]  += __shfl_xor_sync(0xffffffffu, si[b],  off);
                        shn[b] += __shfl_xor_sync(0xffffffffu, shn[b], off);
                    }
                }
                if (lane < 8) {
                    int b = b0 + lane;
                    float r = sigmoidf_(sr[lane] + __ldg(&b_ih[u])          + __ldg(&b_hh[u]));
                    float z = sigmoidf_(sz[lane] + __ldg(&b_ih[Gg + u])     + __ldg(&b_hh[Gg + u]));
                    float n = tanhf((si[lane] + __ldg(&b_ih[2 * Gg + u])) +
                                    r * (shn[lane] + __ldg(&b_hh[2 * Gg + u])));
                    float hold = sm.sh[b * Gg + u];
                    g_h[pb ^ 1][b * Gg + u] = (1.0f - z) * n + z * hold;
                }
            }
        }
        grid_barrier(++target);

        // ================= P2: hid = relu(h_new @ W_hid.T + b_hid) =================
        {
            const float4* src = (const float4*)g_h[pb ^ 1];
            float4* dst = (float4*)sm.sh;
            for (int i = tid; i < (Bb * Gg) / 4; i += NT) dst[i] = __ldcg(src + i);
        }
        __syncthreads();
        {
            const int u0 = (bid * Hh) / NB, u1 = ((bid + 1) * Hh) / NB;
            const int u  = u0 + (wid >> 1);
            if (u < u1) {
                const int b0 = (wid & 1) * 8;
                float acc[8];
#pragma unroll
                for (int b = 0; b < 8; ++b) acc[b] = 0.f;
#pragma unroll
                for (int k = 0; k < 4; ++k) {
                    int c4 = lane + 32 * k;
                    float4 w = __ldg((const float4*)(W_hid + (size_t)u * Gg) + c4);
#pragma unroll
                    for (int b = 0; b < 8; ++b) {
                        float4 h4 = ((const float4*)(sm.sh + (b0 + b) * Gg))[c4];
                        acc[b] = fmaf(w.x, h4.x, fmaf(w.y, h4.y, fmaf(w.z, h4.z, fmaf(w.w, h4.w, acc[b]))));
                    }
                }
#pragma unroll
                for (int off = 16; off; off >>= 1)
#pragma unroll
                    for (int b = 0; b < 8; ++b)
                        acc[b] += __shfl_xor_sync(0xffffffffu, acc[b], off);
                if (lane < 8) {
                    int b = b0 + lane;
                    g_hid[b * Hh + u] = fmaxf(acc[lane] + __ldg(&b_hid[u]), 0.0f);
                }
            }
        }
        grid_barrier(++target);

        // ================= P3: logits + gumbel + val =================
        {
            const float4* src = (const float4*)g_hid;
            float4* dst = (float4*)sm.sh;
            for (int i = tid; i < (Bb * Hh) / 4; i += NT) dst[i] = __ldcg(src + i);
        }
        __syncthreads();
        {
            // per-step JAX key: split(key(1), T)[t] = threefry((0,1),(0,t))
            unsigned kt0, kt1;
            tf2x32(0u, 1u, 0u, (unsigned)t, kt0, kt1);

            const int v0 = (bid * Vv) / NB, v1 = ((bid + 1) * Vv) / NB;
            const int v  = v0 + (wid >> 2);           // 4 warps per v, b quartered
            if (v < v1) {
                const int b0 = (wid & 3) * 4;
                float acc[4];
#pragma unroll
                for (int b = 0; b < 4; ++b) acc[b] = 0.f;
#pragma unroll
                for (int k = 0; k < 4; ++k) {
                    int c4 = lane + 32 * k;
                    float4 w = __ldg((const float4*)(W_out + (size_t)v * Hh) + c4);
#pragma unroll
                    for (int b = 0; b < 4; ++b) {
                        float4 h4 = ((const float4*)(sm.sh + (b0 + b) * Hh))[c4];
                        acc[b] = fmaf(w.x, h4.x, fmaf(w.y, h4.y, fmaf(w.z, h4.z, fmaf(w.w, h4.w, acc[b]))));
                    }
                }
#pragma unroll
                for (int off = 16; off; off >>= 1)
#pragma unroll
                    for (int b = 0; b < 4; ++b)
                        acc[b] += __shfl_xor_sync(0xffffffffu, acc[b], off);
                if (lane < 4) {
                    int b = b0 + lane;
                    float logit = acc[lane] + __ldg(&b_out[v]);
                    out_logits[((size_t)b * Tt + t) * Vv + v] = logit;
                    // partitionable threefry random_bits(key_t, 32, (16,256)):
                    // counter = linear index m (hi=0, lo=m), bits = w0 ^ w1
                    unsigned m = (unsigned)(b * Vv + v);
                    unsigned r0, r1;
                    tf2x32(kt0, kt1, 0u, m, r0, r1);
                    unsigned bits = r0 ^ r1;
                    float f = __uint_as_float((bits >> 9) | 0x3f800000u) - 1.0f;
                    float u01 = fmaxf(f, 1.17549435e-38f);          // uniform(tiny, 1)
                    float gum = -logf(-logf(u01));                  // gumbel
                    g_val[b * Vv + v] = logit + gum;
                }
            }
        }
        grid_barrier(++target);
    }

    // ================= epilogue: last sample + h_final =================
    if (bid == 0 && wid < 8) {
#pragma unroll
        for (int rep = 0; rep < 2; ++rep) {
            int b = wid + rep * 8;
            int besti = warp_argmax_b(b, lane);
            if (lane == 0) out_samples[b * Tt + (Tt - 1)] = (float)besti;
        }
    }
    // after t=1999 (odd), h_new lives in g_h[0]
    for (int i = bid * NT + tid; i < Bb * Gg; i += NB * NT)
        out_hfinal[i] = __ldcg(&g_h[0][i]);
}

extern "C" void kernel_launch(void* const* d_in, const int* in_sizes, int n_in,
                              void* d_out, int out_size) {
    const float* cond  = (const float*)d_in[0];
    const float* h0    = (const float*)d_in[1];
    const float* W_ih  = (const float*)d_in[2];
    const float* W_hh  = (const float*)d_in[3];
    const float* b_ih  = (const float*)d_in[4];
    const float* b_hh  = (const float*)d_in[5];
    const float* W_hid = (const float*)d_in[6];
    const float* b_hid = (const float*)d_in[7];
    const float* W_out = (const float*)d_in[8];
    const float* b_out = (const float*)d_in[9];
    const float* emb   = (const float*)d_in[10];
    float* out = (float*)d_out;

    wavernn_persistent<<<NB, NT>>>(cond, h0, W_ih, W_hh, b_ih, b_hh,
                                   W_hid, b_hid, W_out, b_out, emb, out);
}

// round 9
// speedup vs baseline: 1.1151x; 1.1151x over previous
#include <cuda_runtime.h>

// Problem sizes
#define NB   128      // persistent grid; 512/NB=4 units per block, 256/NB=2 logit rows
#define NT   256
#define Bb   16
#define Tt   2000
#define Cc   128
#define Gg   512
#define Hh   512
#define Vv   256

// ---------------- global scratch (no allocations allowed) ----------------
__device__ __align__(16) float g_h[2][Bb * Gg];    // double-buffered hidden state
__device__ __align__(16) float g_hid[Bb * Hh];
__device__ __align__(16) float g_val[Bb * Vv];     // logits + gumbel (for argmax)
__device__ unsigned long long  g_cnt;              // MONOTONIC arrival counter (never reset)
__device__ unsigned long long  g_gen;              // barrier generation (monotonic)
// invariant at quiescence: g_cnt == g_gen * NB    (both start at 0)

struct __align__(16) Smem {
    float sh[Bb * Gg];     // 32KB: staged h (P1) / h_new (P2) / hid (P3)
    float sx[Bb * Cc];     // 8KB : staged x = cond_t + embedding[prev]
    int   sprev[Bb];
    unsigned long long gen0;
};

// ---------------- threefry2x32 (exact JAX semantics) ----------------
__device__ __forceinline__ unsigned rotl32(unsigned x, int r) {
    return (x << r) | (x >> (32 - r));
}

__device__ __forceinline__ void tf2x32(unsigned k0, unsigned k1,
                                       unsigned x0, unsigned x1,
                                       unsigned& o0, unsigned& o1) {
    unsigned ks2 = k0 ^ k1 ^ 0x1BD11BDAu;
    x0 += k0; x1 += k1;
    x0 += x1; x1 = rotl32(x1, 13); x1 ^= x0;
    x0 += x1; x1 = rotl32(x1, 15); x1 ^= x0;
    x0 += x1; x1 = rotl32(x1, 26); x1 ^= x0;
    x0 += x1; x1 = rotl32(x1, 6);  x1 ^= x0;
    x0 += k1; x1 += ks2 + 1u;
    x0 += x1; x1 = rotl32(x1, 17); x1 ^= x0;
    x0 += x1; x1 = rotl32(x1, 29); x1 ^= x0;
    x0 += x1; x1 = rotl32(x1, 16); x1 ^= x0;
    x0 += x1; x1 = rotl32(x1, 24); x1 ^= x0;
    x0 += ks2; x1 += k0 + 2u;
    x0 += x1; x1 = rotl32(x1, 13); x1 ^= x0;
    x0 += x1; x1 = rotl32(x1, 15); x1 ^= x0;
    x0 += x1; x1 = rotl32(x1, 26); x1 ^= x0;
    x0 += x1; x1 = rotl32(x1, 6);  x1 ^= x0;
    x0 += k0; x1 += k1 + 3u;
    x0 += x1; x1 = rotl32(x1, 17); x1 ^= x0;
    x0 += x1; x1 = rotl32(x1, 29); x1 ^= x0;
    x0 += x1; x1 = rotl32(x1, 16); x1 ^= x0;
    x0 += x1; x1 = rotl32(x1, 24); x1 ^= x0;
    x0 += k1; x1 += ks2 + 4u;
    x0 += x1; x1 = rotl32(x1, 13); x1 ^= x0;
    x0 += x1; x1 = rotl32(x1, 15); x1 ^= x0;
    x0 += x1; x1 = rotl32(x1, 26); x1 ^= x0;
    x0 += x1; x1 = rotl32(x1, 6);  x1 ^= x0;
    x0 += ks2; x1 += k0 + 5u;
    o0 = x0; o1 = x1;
}

__device__ __forceinline__ float sigmoidf_(float x) {
    return 1.0f / (1.0f + expf(-x));
}

// ---------------- grid barrier: monotonic count, acq/rel g_gen ----------------
__device__ __forceinline__ unsigned long long gen_acquire() {
    unsigned long long v;
    asm volatile("ld.acquire.gpu.global.u64 %0, [%1];" : "=l"(v) : "l"(&g_gen));
    return v;
}

__device__ __forceinline__ void gen_release(unsigned long long v) {
    asm volatile("st.release.gpu.global.u64 [%0], %1;" :: "l"(&g_gen), "l"(v) : "memory");
}

__device__ __forceinline__ void grid_barrier(unsigned long long target) {
    __threadfence();      // publish this thread's prior global writes (cumulative release)
    __syncthreads();
    if (threadIdx.x == 0) {
        unsigned long long c = atomicAdd(&g_cnt, 1ULL);
        if (c == target * (unsigned long long)NB - 1ULL) {
            gen_release(target);                 // last arriver releases
        } else {
            while (gen_acquire() < target) { }   // acquire-load poll (no atomic-ALU serialization)
        }
    }
    __syncthreads();
}

// warp-cooperative argmax over g_val[b][0..255], first-index tie-break (jnp.argmax)
__device__ __forceinline__ int warp_argmax_b(int b, int lane) {
    float bestv = -1e30f; int besti = 0;
#pragma unroll
    for (int k = 0; k < 8; ++k) {
        int v = lane + 32 * k;
        float x = __ldcg(&g_val[b * Vv + v]);
        if (x > bestv) { bestv = x; besti = v; }
    }
#pragma unroll
    for (int off = 16; off; off >>= 1) {
        float ov = __shfl_xor_sync(0xffffffffu, bestv, off);
        int   oi = __shfl_xor_sync(0xffffffffu, besti, off);
        if (ov > bestv || (ov == bestv && oi < besti)) { bestv = ov; besti = oi; }
    }
    return besti;
}

__global__ void __launch_bounds__(NT, 1)
wavernn_persistent(const float* __restrict__ cond,
                   const float* __restrict__ h0,
                   const float* __restrict__ W_ih,
                   const float* __restrict__ W_hh,
                   const float* __restrict__ b_ih,
                   const float* __restrict__ b_hh,
                   const float* __restrict__ W_hid,
                   const float* __restrict__ b_hid,
                   const float* __restrict__ W_out,
                   const float* __restrict__ b_out,
                   const float* __restrict__ emb,
                   float* __restrict__ out) {
    __shared__ Smem sm;
    const int tid  = threadIdx.x;
    const int bid  = blockIdx.x;
    const int wid  = tid >> 5;
    const int lane = tid & 31;

    // barrier generation base for this launch: g_gen cannot advance until every
    // block of THIS launch arrives at barrier 1, and each block reads the base
    // before its first arrival -> all blocks observe the same gen0.
    if (tid == 0) sm.gen0 = gen_acquire();
    __syncthreads();
    unsigned long long target = sm.gen0;

    float* out_logits  = out;                                // [B][T][V]
    float* out_samples = out + (size_t)Bb * Tt * Vv;         // [B][T]
    float* out_hfinal  = out + (size_t)Bb * Tt * Vv + (size_t)Bb * Tt; // [B][G]

    // ---- init: h[0] = h0 ----
    for (int i = bid * NT + tid; i < Bb * Gg; i += NB * NT)
        __stcg(&g_h[0][i], h0[i]);
    grid_barrier(++target);

    for (int t = 0; t < Tt; ++t) {
        const int pb = t & 1;           // g_h[pb] = current h, g_h[pb^1] = h_new

        // ================= P1 prologue: prev (argmax of last step) + stage x, h =================
        if (t == 0) {
            if (tid < Bb) sm.sprev[tid] = Vv / 2;   // mid-bucket
        } else if (wid < 8) {
#pragma unroll
            for (int rep = 0; rep < 2; ++rep) {
                int b = wid + rep * 8;
                int besti = warp_argmax_b(b, lane);
                if (lane == 0) {
                    sm.sprev[b] = besti;
                    if (bid == 0) out_samples[b * Tt + (t - 1)] = (float)besti;
                }
            }
        }
        __syncthreads();

        // stage x = cond[:, t, :] + embedding[prev]
        for (int i = tid; i < Bb * Cc; i += NT) {
            int b = i >> 7, c = i & (Cc - 1);
            sm.sx[i] = __ldg(&cond[((size_t)b * Tt + t) * Cc + c]) +
                       __ldg(&emb[(size_t)sm.sprev[b] * Cc + c]);
        }
        // stage h (cross-SM data: L2 loads)
        {
            const float4* src = (const float4*)g_h[pb];
            float4* dst = (float4*)sm.sh;
            for (int i = tid; i < (Bb * Gg) / 4; i += NT) dst[i] = __ldcg(src + i);
        }
        __syncthreads();

        // ================= P1: fused GRU gates + h update (u = bid*4 + wid/2) =================
        {
            const int u  = (bid << 2) + (wid >> 1);
            const int b0 = (wid & 1) * 8;
            float sr[8], sz[8], si[8], shn[8];
#pragma unroll
            for (int b = 0; b < 8; ++b) { sr[b] = 0.f; sz[b] = 0.f; si[b] = 0.f; shn[b] = 0.f; }

            // x part: W_ih rows u (r), G+u (z), 2G+u (n); row = 32 float4
            {
                float4 wr = __ldg((const float4*)(W_ih + (size_t)u * Cc) + lane);
                float4 wz = __ldg((const float4*)(W_ih + (size_t)(Gg + u) * Cc) + lane);
                float4 wn = __ldg((const float4*)(W_ih + (size_t)(2 * Gg + u) * Cc) + lane);
#pragma unroll
                for (int b = 0; b < 8; ++b) {
                    float4 x4 = ((const float4*)(sm.sx + (b0 + b) * Cc))[lane];
                    sr[b] = fmaf(wr.x, x4.x, fmaf(wr.y, x4.y, fmaf(wr.z, x4.z, fmaf(wr.w, x4.w, sr[b]))));
                    sz[b] = fmaf(wz.x, x4.x, fmaf(wz.y, x4.y, fmaf(wz.z, x4.z, fmaf(wz.w, x4.w, sz[b]))));
                    si[b] = fmaf(wn.x, x4.x, fmaf(wn.y, x4.y, fmaf(wn.z, x4.z, fmaf(wn.w, x4.w, si[b]))));
                }
            }
            // h part: W_hh rows u, G+u, 2G+u; row = 128 float4
#pragma unroll
            for (int k = 0; k < 4; ++k) {
                int c4 = lane + 32 * k;
                float4 wr = __ldg((const float4*)(W_hh + (size_t)u * Gg) + c4);
                float4 wz = __ldg((const float4*)(W_hh + (size_t)(Gg + u) * Gg) + c4);
                float4 wn = __ldg((const float4*)(W_hh + (size_t)(2 * Gg + u) * Gg) + c4);
#pragma unroll
                for (int b = 0; b < 8; ++b) {
                    float4 h4 = ((const float4*)(sm.sh + (b0 + b) * Gg))[c4];
                    sr[b]  = fmaf(wr.x, h4.x, fmaf(wr.y, h4.y, fmaf(wr.z, h4.z, fmaf(wr.w, h4.w, sr[b]))));
                    sz[b]  = fmaf(wz.x, h4.x, fmaf(wz.y, h4.y, fmaf(wz.z, h4.z, fmaf(wz.w, h4.w, sz[b]))));
                    shn[b] = fmaf(wn.x, h4.x, fmaf(wn.y, h4.y, fmaf(wn.z, h4.z, fmaf(wn.w, h4.w, shn[b]))));
                }
            }
            // butterfly reduce all accumulators across the warp
#pragma unroll
            for (int off = 16; off; off >>= 1) {
#pragma unroll
                for (int b = 0; b < 8; ++b) {
                    sr[b]  += __shfl_xor_sync(0xffffffffu, sr[b],  off);
                    sz[b]  += __shfl_xor_sync(0xffffffffu, sz[b],  off);
                    si[b]  += __shfl_xor_sync(0xffffffffu, si[b],  off);
                    shn[b] += __shfl_xor_sync(0xffffffffu, shn[b], off);
                }
            }
            if (lane < 8) {
                int b = b0 + lane;
                float r = sigmoidf_(sr[lane] + __ldg(&b_ih[u])          + __ldg(&b_hh[u]));
                float z = sigmoidf_(sz[lane] + __ldg(&b_ih[Gg + u])     + __ldg(&b_hh[Gg + u]));
                float n = tanhf((si[lane] + __ldg(&b_ih[2 * Gg + u])) +
                                r * (shn[lane] + __ldg(&b_hh[2 * Gg + u])));
                float hold = sm.sh[b * Gg + u];
                __stcg(&g_h[pb ^ 1][b * Gg + u], (1.0f - z) * n + z * hold);
            }
        }
        grid_barrier(++target);

        // ================= P2: hid = relu(h_new @ W_hid.T + b_hid) =================
        {
            const float4* src = (const float4*)g_h[pb ^ 1];
            float4* dst = (float4*)sm.sh;
            for (int i = tid; i < (Bb * Gg) / 4; i += NT) dst[i] = __ldcg(src + i);
        }
        __syncthreads();
        {
            const int u  = (bid << 2) + (wid >> 1);
            const int b0 = (wid & 1) * 8;
            float acc[8];
#pragma unroll
            for (int b = 0; b < 8; ++b) acc[b] = 0.f;
#pragma unroll
            for (int k = 0; k < 4; ++k) {
                int c4 = lane + 32 * k;
                float4 w = __ldg((const float4*)(W_hid + (size_t)u * Gg) + c4);
#pragma unroll
                for (int b = 0; b < 8; ++b) {
                    float4 h4 = ((const float4*)(sm.sh + (b0 + b) * Gg))[c4];
                    acc[b] = fmaf(w.x, h4.x, fmaf(w.y, h4.y, fmaf(w.z, h4.z, fmaf(w.w, h4.w, acc[b]))));
                }
            }
#pragma unroll
            for (int off = 16; off; off >>= 1)
#pragma unroll
                for (int b = 0; b < 8; ++b)
                    acc[b] += __shfl_xor_sync(0xffffffffu, acc[b], off);
            if (lane < 8) {
                int b = b0 + lane;
                __stcg(&g_hid[b * Hh + u], fmaxf(acc[lane] + __ldg(&b_hid[u]), 0.0f));
            }
        }
        grid_barrier(++target);

        // ================= P3: logits + gumbel + val =================
        {
            const float4* src = (const float4*)g_hid;
            float4* dst = (float4*)sm.sh;
            for (int i = tid; i < (Bb * Hh) / 4; i += NT) dst[i] = __ldcg(src + i);
        }
        __syncthreads();
        {
            // per-step JAX key: split(key(1), T)[t] = threefry((0,1),(0,t))
            unsigned kt0, kt1;
            tf2x32(0u, 1u, 0u, (unsigned)t, kt0, kt1);

            const int v  = (bid << 1) + (wid >> 2);   // 2 logit rows per block
            const int b0 = (wid & 3) * 4;
            float acc[4];
#pragma unroll
            for (int b = 0; b < 4; ++b) acc[b] = 0.f;
#pragma unroll
            for (int k = 0; k < 4; ++k) {
                int c4 = lane + 32 * k;
                float4 w = __ldg((const float4*)(W_out + (size_t)v * Hh) + c4);
#pragma unroll
                for (int b = 0; b < 4; ++b) {
                    float4 h4 = ((const float4*)(sm.sh + (b0 + b) * Hh))[c4];
                    acc[b] = fmaf(w.x, h4.x, fmaf(w.y, h4.y, fmaf(w.z, h4.z, fmaf(w.w, h4.w, acc[b]))));
                }
            }
#pragma unroll
            for (int off = 16; off; off >>= 1)
#pragma unroll
                for (int b = 0; b < 4; ++b)
                    acc[b] += __shfl_xor_sync(0xffffffffu, acc[b], off);
            if (lane < 4) {
                int b = b0 + lane;
                float logit = acc[lane] + __ldg(&b_out[v]);
                out_logits[((size_t)b * Tt + t) * Vv + v] = logit;
                // partitionable threefry random_bits(key_t, 32, (16,256)):
                // counter = linear index m (hi=0, lo=m), bits = w0 ^ w1
                unsigned m = (unsigned)(b * Vv + v);
                unsigned r0, r1;
                tf2x32(kt0, kt1, 0u, m, r0, r1);
                unsigned bits = r0 ^ r1;
                float f = __uint_as_float((bits >> 9) | 0x3f800000u) - 1.0f;
                float u01 = fmaxf(f, 1.17549435e-38f);          // uniform(tiny, 1)
                float gum = -logf(-logf(u01));                  // gumbel
                __stcg(&g_val[b * Vv + v], logit + gum);
            }
        }
        grid_barrier(++target);
    }

    // ================= epilogue: last sample + h_final =================
    if (bid == 0 && wid < 8) {
#pragma unroll
        for (int rep = 0; rep < 2; ++rep) {
            int b = wid + rep * 8;
            int besti = warp_argmax_b(b, lane);
            if (lane == 0) out_samples[b * Tt + (Tt - 1)] = (float)besti;
        }
    }
    // after t=1999 (odd), h_new lives in g_h[0]
    for (int i = bid * NT + tid; i < Bb * Gg; i += NB * NT)
        out_hfinal[i] = __ldcg(&g_h[0][i]);
}

extern "C" void kernel_launch(void* const* d_in, const int* in_sizes, int n_in,
                              void* d_out, int out_size) {
    const float* cond  = (const float*)d_in[0];
    const float* h0    = (const float*)d_in[1];
    const float* W_ih  = (const float*)d_in[2];
    const float* W_hh  = (const float*)d_in[3];
    const float* b_ih  = (const float*)d_in[4];
    const float* b_hh  = (const float*)d_in[5];
    const float* W_hid = (const float*)d_in[6];
    const float* b_hid = (const float*)d_in[7];
    const float* W_out = (const float*)d_in[8];
    const float* b_out = (const float*)d_in[9];
    const float* emb   = (const float*)d_in[10];
    float* out = (float*)d_out;

    wavernn_persistent<<<NB, NT>>>(cond, h0, W_ih, W_hh, b_ih, b_hh,
                                   W_hid, b_hid, W_out, b_out, emb, out);
}